// round 6
// baseline (speedup 1.0000x reference)
#include <cuda_runtime.h>
#include <cstdint>

#define TT     2190
#define NWARM  365
#define NMAIN  1825
#define NG     10000
#define NH     5000                     // 2 cells per thread
#define KER    15
#define CH     25
#define BLK    64
#define DPF    12                       // prefetch depth in steps
#define RING   16                       // smem ring slots (power of 2 > DPF)
#define ROWB   (NG * 3 * 4)             // bytes per time row
#define SLOTF  (BLK * 6)                // floats per ring slot (2 cells x 3)
#define SLOTB  (SLOTF * 4)              // bytes per ring slot

// scratch (device globals: the sanctioned no-alloc workaround)
__device__ float g_q[NMAIN * NG];       // raw simulated discharge, 73 MB
__device__ float g_uh[KER * NG];        // per-cell unit hydrograph

// ---------------------------------------------------------------------------
struct Cell {
    float beta, inv_fc, fc, inv_lpfc, pperc, uzl, tt, cfmax, mcf, cfr, cwh,
          k0, omk1, omk2;
    float sp, mw, sm, suz, slz;
};

__device__ __forceinline__ void cell_init(Cell& c, const float* __restrict__ par, int g)
{
    float raw[14];
    #pragma unroll
    for (int i = 0; i < 14; ++i) raw[i] = par[g * 14 + i];
    c.beta    = 1.0f   + raw[0]  * 5.0f;
    c.fc      = 50.0f  + raw[1]  * 950.0f;
    c.k0      = 0.05f  + raw[2]  * 0.85f;
    float k1  = 0.01f  + raw[3]  * 0.49f;
    float k2  = 0.001f + raw[4]  * 0.199f;
    float lp  = 0.2f   + raw[5]  * 0.8f;
    c.pperc   =          raw[6]  * 10.0f;
    c.uzl     =          raw[7]  * 100.0f;
    c.tt      = -2.5f  + raw[8]  * 5.0f;
    c.cfmax   = 0.5f   + raw[9]  * 9.5f;
    c.cfr     =          raw[10] * 0.1f;
    c.cwh     =          raw[11] * 0.2f;
    c.mcf     = -c.cfmax * c.tt;
    c.inv_fc  = 1.0f / c.fc;
    c.inv_lpfc= 1.0f / (lp * c.fc);
    c.omk1    = 1.0f - k1;
    c.omk2    = 1.0f - k2;
    c.sp = 0.001f; c.mw = 0.001f; c.sm = 0.001f; c.suz = 0.001f; c.slz = 0.001f;
}

// one HBV timestep; chain-minimized, clamp-free where invariants allow
__device__ __forceinline__ float step(Cell& c, float precip, float pet, float tm)
{
    float rain = (tm >= c.tt) ? precip : 0.0f;
    float snow = precip - rain;
    float d    = fmaf(c.cfmax, tm, c.mcf);               // cfmax*(tm-tt)
    float sp1  = c.sp + snow;
    float melt = fminf(fmaxf(d, 0.0f), sp1);
    float mw1  = c.mw + melt;
    float cfrd = c.cfr * d;
    float refr = fminf(fmaxf(-cfrd, 0.0f), mw1);         // cfr*cfmax*(tt-tm)
    float mw2  = mw1 - refr;
    float sp2  = sp1 - melt + refr;
    float ts   = fmaxf(fmaf(-c.cwh, sp2, mw2), 0.0f);
    c.mw = mw2 - ts;
    c.sp = sp2;
    // sm <= fc and beta >= 1  =>  sw <= 1 structurally; no clamp needed
    float sw   = __powf(c.sm * c.inv_fc, c.beta);
    float rts  = rain + ts;
    float srts = c.sm + rts;                             // off sw-chain
    float sm1  = fmaf(-rts, sw, srts);                   // sm + rts*(1-sw)
    float rech = rts * sw;
    float sm2  = fminf(sm1, c.fc);
    float exc  = sm1 - sm2;                              // max(sm1-fc,0)
    float pil  = pet * c.inv_lpfc;                       // off sm-chain
    float t2   = fminf(sm2 * pil, pet);                  // pet*clip(ef,0,1)
    c.sm       = fmaxf(sm2 - t2, 1e-5f);                 // sm - min(sm, pet*ef)
    float suz2 = c.suz + rech + exc;
    float perc = fminf(suz2, c.pperc);
    float suz3 = suz2 - perc;
    float q0   = c.k0 * fmaxf(suz3 - c.uzl, 0.0f);
    float suzn = (suz3 - q0) * c.omk1;                   // q0+q1 = suz3 - suzn
    float slz1 = c.slz + perc;
    float slzn = slz1 * c.omk2;                          // q2 = slz1 - slzn
    c.suz = suzn;
    c.slz = slzn;
    return (suz3 - suzn) + (slz1 - slzn);
}

// ---------------------------------------------------------------------------
__device__ __forceinline__ void cp4(uint32_t dst, const char* src)
{
    asm volatile("cp.async.ca.shared.global [%0], [%1], 4;"
                 :: "r"(dst), "l"(src));
}
__device__ __forceinline__ void cp_commit()
{
    asm volatile("cp.async.commit_group;");
}
__device__ __forceinline__ void cp_wait_keep11()
{
    asm volatile("cp.async.wait_group 11;");   // DPF-1
}

// ---------------------------------------------------------------------------
// K0: gamma unit hydrograph per cell
// ---------------------------------------------------------------------------
__global__ void __launch_bounds__(256)
uh_kernel(const float* __restrict__ par)
{
    int g = blockIdx.x * blockDim.x + threadIdx.x;
    if (g >= NG) return;
    float a   = fmaf(par[g * 14 + 12], 2.9f, 0.1f);
    float th  = fmaf(par[g * 14 + 13], 6.5f, 0.5f);
    float am1 = a - 1.0f;
    float ith = 1.0f / th;

    float w[KER], s = 0.0f;
    #pragma unroll
    for (int k = 0; k < KER; ++k) {
        float tk = (float)k + 0.5f;
        w[k] = __expf(fmaf(am1, __logf(tk), -tk * ith));
        s += w[k];
    }
    float inv = 1.0f / s;
    #pragma unroll
    for (int k = 0; k < KER; ++k) g_uh[k * NG + g] = w[k] * inv;
}

// ---------------------------------------------------------------------------
// K1: sequential HBV scan, TWO cells/thread over a cp.async smem ring.
// cp.async removes scoreboard-slot aliasing (proved in R5); the second,
// independent chain fills the MUFU/FMA dependency bubbles of the first.
// Each thread copies only its OWN 24B/step -> no __syncthreads anywhere.
// ---------------------------------------------------------------------------
__global__ void __launch_bounds__(64, 1)
hbv_scan_kernel(const float* __restrict__ x, const float* __restrict__ par)
{
    __shared__ float ring[RING * SLOTF];

    int tid = threadIdx.x;
    int i   = blockIdx.x * BLK + tid;
    bool active = (i < NH);
    int iA  = active ? i : (NH - 1);
    int gA  = iA, gB = iA + NH;

    Cell cA, cB;
    cell_init(cA, par, gA);
    cell_init(cB, par, gB);

    // smem addresses of this thread's triples within slot 0
    uint32_t sbase = (uint32_t)__cvta_generic_to_shared(ring);
    uint32_t sbA = sbase + (uint32_t)tid * 12u;
    uint32_t sbB = sbase + (uint32_t)(BLK * 12) + (uint32_t)tid * 12u;
    const float* __restrict__ myA = ring + tid * 3;
    const float* __restrict__ myB = ring + BLK * 3 + tid * 3;

    const char* srcA = (const char*)x + (size_t)gA * 12u;
    const char* srcB = (const char*)x + (size_t)gB * 12u;

    // ---- prologue: prefetch steps 0..DPF-1 ----
    #pragma unroll
    for (int s = 0; s < DPF; ++s) {
        uint32_t dA = sbA + (uint32_t)s * SLOTB;
        uint32_t dB = sbB + (uint32_t)s * SLOTB;
        if (active) {
            cp4(dA, srcA); cp4(dA + 4, srcA + 4); cp4(dA + 8, srcA + 8);
            cp4(dB, srcB); cp4(dB + 4, srcB + 4); cp4(dB + 8, srcB + 8);
        }
        cp_commit();
        srcA += ROWB; srcB += ROWB;
    }

    int rd = 0, wr = DPF;

    // ---- warmup: 365 steps, copies unconditional (last target step 376) ----
    #pragma unroll 1
    for (int it = 0; it < NWARM / 5; ++it) {
        #pragma unroll
        for (int u = 0; u < 5; ++u) {
            cp_wait_keep11();
            int rb = rd * SLOTF;
            float pa = myA[rb + 0], ea = myA[rb + 1], ta = myA[rb + 2];
            float pb = myB[rb + 0], eb = myB[rb + 1], tb = myB[rb + 2];
            uint32_t dA = sbA + (uint32_t)wr * SLOTB;
            uint32_t dB = sbB + (uint32_t)wr * SLOTB;
            if (active) {
                cp4(dA, srcA); cp4(dA + 4, srcA + 4); cp4(dA + 8, srcA + 8);
                cp4(dB, srcB); cp4(dB + 4, srcB + 4); cp4(dB + 8, srcB + 8);
            }
            cp_commit();
            srcA += ROWB; srcB += ROWB;
            rd = (rd + 1) & (RING - 1);
            wr = (wr + 1) & (RING - 1);
            (void)step(cA, pa, ea, ta);
            (void)step(cB, pb, eb, tb);
        }
    }

    // ---- main: 1825 steps, copies guarded near the end of the series ----
    float* __restrict__ qpA = g_q + gA;
    float* __restrict__ qpB = g_q + gB;
    int ncpy = NWARM + DPF;
    #pragma unroll 1
    for (int it = 0; it < NMAIN / 5; ++it) {
        #pragma unroll
        for (int u = 0; u < 5; ++u) {
            cp_wait_keep11();
            int rb = rd * SLOTF;
            float pa = myA[rb + 0], ea = myA[rb + 1], ta = myA[rb + 2];
            float pb = myB[rb + 0], eb = myB[rb + 1], tb = myB[rb + 2];
            uint32_t dA = sbA + (uint32_t)wr * SLOTB;
            uint32_t dB = sbB + (uint32_t)wr * SLOTB;
            if (active && ncpy < TT) {
                cp4(dA, srcA); cp4(dA + 4, srcA + 4); cp4(dA + 8, srcA + 8);
                cp4(dB, srcB); cp4(dB + 4, srcB + 4); cp4(dB + 8, srcB + 8);
            }
            cp_commit();                          // empty groups keep FIFO depth
            srcA += ROWB; srcB += ROWB;
            ncpy++;
            rd = (rd + 1) & (RING - 1);
            wr = (wr + 1) & (RING - 1);
            float qa = step(cA, pa, ea, ta);
            float qb = step(cB, pb, eb, tb);
            if (active) { *qpA = qa; *qpB = qb; }
            qpA += NG; qpB += NG;
        }
    }
    asm volatile("cp.async.wait_group 0;");      // drain before exit
}

// ---------------------------------------------------------------------------
// K2: 15-tap causal convolution, fully parallel. Thread = (cell, 25-step chunk).
// ---------------------------------------------------------------------------
__global__ void __launch_bounds__(256)
conv_kernel(float* __restrict__ out)
{
    int g = blockIdx.x * blockDim.x + threadIdx.x;
    if (g >= NG) return;
    int t0 = blockIdx.y * CH;

    float uh[KER];
    #pragma unroll
    for (int k = 0; k < KER; ++k) uh[k] = g_uh[k * NG + g];

    float w[KER - 1];
    #pragma unroll
    for (int j = 0; j < KER - 1; ++j) {
        int t = t0 - 1 - j;
        w[j] = (t >= 0) ? g_q[t * NG + g] : 0.0f;
    }

    #pragma unroll
    for (int s = 0; s < CH; ++s) {
        float qn = g_q[(t0 + s) * NG + g];
        float o  = uh[0] * qn;
        #pragma unroll
        for (int j = 0; j < KER - 1; ++j)
            o = fmaf(uh[j + 1], w[j], o);
        out[(t0 + s) * NG + g] = o;
        #pragma unroll
        for (int j = KER - 2; j > 0; --j) w[j] = w[j - 1];
        w[0] = qn;
    }
}

// ---------------------------------------------------------------------------
extern "C" void kernel_launch(void* const* d_in, const int* in_sizes, int n_in,
                              void* d_out, int out_size)
{
    const float* x   = (const float*)d_in[0];   // (2190, 10000, 3) f32
    const float* par = (const float*)d_in[1];   // (10000, 14) f32
    float*       out = (float*)d_out;           // (1825, 10000, 1) f32

    uh_kernel<<<(NG + 255) / 256, 256>>>(par);
    hbv_scan_kernel<<<(NH + BLK - 1) / BLK, BLK>>>(x, par);
    conv_kernel<<<dim3((NG + 255) / 256, NMAIN / CH), 256>>>(out);
}